// round 4
// baseline (speedup 1.0000x reference)
#include <cuda_runtime.h>
#include <cstdint>

#define KC    8192
#define DIM   64
#define NROWS 32768
#define BM    64      // rows per block
#define BK    128     // codes per smem chunk
#define CBS   68      // padded floats per code row in smem (272B -> 2-way conflicts only)
#define TXN   16      // threads along code dim
#define RR    4       // rows per thread
#define CC    8       // codes per thread
#define NCHUNK (KC / BK)

#define SMEM_BYTES ((BM*DIM + 2*BK*CBS) * 4 + BM * 4)

__device__ float g_e2[KC];

// ---------------- helpers ----------------
__device__ __forceinline__ unsigned long long ffma2(unsigned long long a,
                                                    unsigned long long b,
                                                    unsigned long long c) {
    unsigned long long d;
    asm("fma.rn.f32x2 %0, %1, %2, %3;" : "=l"(d) : "l"(a), "l"(b), "l"(c));
    return d;
}
__device__ __forceinline__ float f2lo(unsigned long long v) {
    return __uint_as_float((unsigned)v);
}
__device__ __forceinline__ float f2hi(unsigned long long v) {
    return __uint_as_float((unsigned)(v >> 32));
}
__device__ __forceinline__ void cp_async16(void* dst, const void* src) {
    unsigned s = (unsigned)__cvta_generic_to_shared(dst);
    asm volatile("cp.async.cg.shared.global [%0], [%1], 16;" :: "r"(s), "l"(src));
}
__device__ __forceinline__ void cp_commit() {
    asm volatile("cp.async.commit_group;");
}

// ---------------- e2 = ||codebook_k||^2 ----------------
__global__ void e2_kernel(const float* __restrict__ cb) {
    int k = blockIdx.x * blockDim.x + threadIdx.x;
    if (k >= KC) return;
    const float4* p = reinterpret_cast<const float4*>(cb + (size_t)k * DIM);
    float s = 0.f;
#pragma unroll
    for (int i = 0; i < DIM / 4; i++) {
        float4 v = p[i];
        s += v.x * v.x + v.y * v.y + v.z * v.z + v.w * v.w;
    }
    g_e2[k] = s;
}

// ---------------- main VQ kernel ----------------
__global__ void vq_kernel(const float* __restrict__ x,
                          const float* __restrict__ cb,
                          float* __restrict__ out_q,
                          float* __restrict__ out_idx,
                          int write_idx) {
    extern __shared__ float smem[];
    float* x_s   = smem;                       // BM*DIM
    float* cb_s0 = smem + BM * DIM;            // BK*CBS
    float* cb_s1 = cb_s0 + BK * CBS;           // BK*CBS
    int*   s_idx = (int*)(cb_s1 + BK * CBS);   // BM

    const int tid  = threadIdx.x;
    const int tx   = tid & 15;
    const int ty   = tid >> 4;
    const int row0 = blockIdx.x * BM;

    // ---- stage: x tile + cb chunk 0 (group 0) ----
#pragma unroll
    for (int i = 0; i < 4; i++) {
        int j = i * 256 + tid;
        int row = j >> 4, q = j & 15;
        cp_async16(x_s + row * DIM + q * 4, x + (size_t)(row0 + row) * DIM + q * 4);
    }
#pragma unroll
    for (int i = 0; i < 8; i++) {
        int j = i * 256 + tid;
        int code = j >> 4, q = j & 15;
        cp_async16(cb_s0 + code * CBS + q * 4, cb + (size_t)code * DIM + q * 4);
    }
    cp_commit();
    // ---- cb chunk 1 (group 1) ----
#pragma unroll
    for (int i = 0; i < 8; i++) {
        int j = i * 256 + tid;
        int code = j >> 4, q = j & 15;
        cp_async16(cb_s1 + code * CBS + q * 4, cb + (size_t)(BK + code) * DIM + q * 4);
    }
    cp_commit();

    float bestd[RR];
    int   besti[RR];
#pragma unroll
    for (int r = 0; r < RR; r++) { bestd[r] = __int_as_float(0x7f800000); besti[r] = 0; }

    const float* xrow = x_s + (ty * RR) * DIM;

    for (int t = 0; t < NCHUNK; t++) {
        asm volatile("cp.async.wait_group 1;");
        __syncthreads();
        const float* cbuf = (t & 1) ? cb_s1 : cb_s0;

        unsigned long long acc[RR][CC];
#pragma unroll
        for (int r = 0; r < RR; r++)
#pragma unroll
            for (int c = 0; c < CC; c++) acc[r][c] = 0ull;

#pragma unroll
        for (int d = 0; d < DIM; d += 4) {
            ulonglong2 xv[RR];
#pragma unroll
            for (int r = 0; r < RR; r++)
                xv[r] = *reinterpret_cast<const ulonglong2*>(xrow + r * DIM + d);
            ulonglong2 cv[CC];
#pragma unroll
            for (int c = 0; c < CC; c++)
                cv[c] = *reinterpret_cast<const ulonglong2*>(cbuf + (tx + c * TXN) * CBS + d);
#pragma unroll
            for (int r = 0; r < RR; r++)
#pragma unroll
                for (int c = 0; c < CC; c++) {
                    acc[r][c] = ffma2(xv[r].x, cv[c].x, acc[r][c]);
                    acc[r][c] = ffma2(xv[r].y, cv[c].y, acc[r][c]);
                }
        }

        __syncthreads();   // everyone done reading this buffer
        if (t + 2 < NCHUNK) {
            float* dst = (t & 1) ? cb_s1 : cb_s0;
#pragma unroll
            for (int i = 0; i < 8; i++) {
                int j = i * 256 + tid;
                int code = j >> 4, q = j & 15;
                cp_async16(dst + code * CBS + q * 4,
                           cb + (size_t)((t + 2) * BK + code) * DIM + q * 4);
            }
        }
        cp_commit();  // empty group is legal on the last two iterations

        // finalize this chunk's 8 codes per thread (overlaps with the async fills)
        const int cbase = t * BK;
#pragma unroll
        for (int c = 0; c < CC; c++) {
            int code = cbase + tx + c * TXN;
            float e2v = __ldg(g_e2 + code);
#pragma unroll
            for (int r = 0; r < RR; r++) {
                float dot  = f2lo(acc[r][c]) + f2hi(acc[r][c]);
                float dist = fmaf(-2.f, dot, e2v);
                // within a thread codes ascend -> strict < keeps first (lowest) index
                if (dist < bestd[r]) { bestd[r] = dist; besti[r] = code; }
            }
        }
    }

    // ---- argmin reduce across the 16 code-lanes (contiguous within warp) ----
#pragma unroll
    for (int m = 8; m; m >>= 1) {
#pragma unroll
        for (int r = 0; r < RR; r++) {
            float od = __shfl_xor_sync(0xffffffffu, bestd[r], m);
            int   oi = __shfl_xor_sync(0xffffffffu, besti[r], m);
            if (od < bestd[r] || (od == bestd[r] && oi < besti[r])) {
                bestd[r] = od; besti[r] = oi;
            }
        }
    }
    if (tx == 0) {
#pragma unroll
        for (int r = 0; r < RR; r++) s_idx[ty * RR + r] = besti[r];
    }
    __syncthreads();

    if (write_idx && tid < BM) out_idx[row0 + tid] = (float)s_idx[tid];

    // cooperative coalesced gather of codebook rows -> x_q (== x_q_st forward value)
#pragma unroll
    for (int i = 0; i < 4; i++) {
        int j = i * 256 + tid;
        int row = j >> 4, q = j & 15;
        float4 v = __ldg(reinterpret_cast<const float4*>(cb + (size_t)s_idx[row] * DIM) + q);
        reinterpret_cast<float4*>(out_q + (size_t)(row0 + row) * DIM)[q] = v;
    }
}

extern "C" void kernel_launch(void* const* d_in, const int* in_sizes, int n_in,
                              void* d_out, int out_size) {
    const float* x  = (const float*)d_in[0];
    const float* cb = (const float*)d_in[1];
    // defensive: identify tensors by size if order differs
    if (n_in >= 2 && in_sizes[0] == KC * DIM && in_sizes[1] == NROWS * DIM) {
        const float* tmp = x; x = cb; cb = tmp;
    }
    float* out = (float*)d_out;
    int write_idx = (out_size >= NROWS * DIM + NROWS) ? 1 : 0;

    cudaFuncSetAttribute(vq_kernel, cudaFuncAttributeMaxDynamicSharedMemorySize, SMEM_BYTES);

    e2_kernel<<<KC / 256, 256>>>(cb);
    vq_kernel<<<NROWS / BM, 256, SMEM_BYTES>>>(x, cb, out, out + (size_t)NROWS * DIM, write_idx);
}

// round 7
// speedup vs baseline: 1.1264x; 1.1264x over previous
#include <cuda_runtime.h>
#include <cstdint>

#define KC    8192
#define DIM   64
#define NROWS 32768
#define BM    64      // rows per block
#define BK    128     // codes per smem chunk
#define NCHUNK (KC / BK)
#define THREADS 256

// smem: x 64*64 + cb 2*128*64 + best 64+64
#define SMEM_BYTES ((BM*DIM + 2*BK*DIM + 2*BM) * 4)

__device__ float g_e2[KC];

// ---------------- helpers ----------------
__device__ __forceinline__ unsigned long long ffma2(unsigned long long a,
                                                    unsigned long long b,
                                                    unsigned long long c) {
    unsigned long long d;
    asm("fma.rn.f32x2 %0, %1, %2, %3;" : "=l"(d) : "l"(a), "l"(b), "l"(c));
    return d;
}
__device__ __forceinline__ float f2lo(unsigned long long v) {
    return __uint_as_float((unsigned)v);
}
__device__ __forceinline__ float f2hi(unsigned long long v) {
    return __uint_as_float((unsigned)(v >> 32));
}
__device__ __forceinline__ void cp_async16(void* dst, const void* src) {
    unsigned s = (unsigned)__cvta_generic_to_shared(dst);
    asm volatile("cp.async.cg.shared.global [%0], [%1], 16;" :: "r"(s), "l"(src));
}
__device__ __forceinline__ void cp_commit() {
    asm volatile("cp.async.commit_group;");
}

// ---------------- e2 = ||codebook_k||^2 ----------------
__global__ void e2_kernel(const float* __restrict__ cb) {
    int k = blockIdx.x * blockDim.x + threadIdx.x;
    if (k >= KC) return;
    const float4* p = reinterpret_cast<const float4*>(cb + (size_t)k * DIM);
    float s = 0.f;
#pragma unroll
    for (int i = 0; i < DIM / 4; i++) {
        float4 v = p[i];
        s += v.x * v.x + v.y * v.y + v.z * v.z + v.w * v.w;
    }
    g_e2[k] = s;
}

// ---------------- main VQ kernel ----------------
// Warp tile: 16 rows x 64 codes. Lanes: cl = lane>>2 (8 code-lanes),
// rl = lane&3 (4 row-lanes). Thread tile: 4 rows x 8 codes.
// XOR-swizzled smem (no padding): unit q of code c at q^(c&15); of row r at q^(r&3).
__global__ void vq_kernel(const float* __restrict__ x,
                          const float* __restrict__ cb,
                          float* __restrict__ out_q,
                          float* __restrict__ out_idx,
                          int write_idx) {
    extern __shared__ float smem[];
    float* x_s   = smem;                      // BM*DIM
    float* cb_s0 = smem + BM * DIM;           // BK*DIM
    float* cb_s1 = cb_s0 + BK * DIM;          // BK*DIM
    float* s_d   = cb_s1 + BK * DIM;          // BM
    int*   s_i   = (int*)(s_d + BM);          // BM

    const int tid   = threadIdx.x;
    const int lane  = tid & 31;
    const int warp  = tid >> 5;
    const int rl    = lane & 3;
    const int cl    = lane >> 2;
    const int wg_r  = warp >> 1;          // 4 row groups of 16 rows
    const int wg_c  = warp & 1;           // 2 code groups of 64 codes
    const int rowbase = wg_r * 16;
    const int row0  = blockIdx.x * BM;

    // ---- stage: x tile (swizzled) + cb chunk 0 ----
#pragma unroll
    for (int i = 0; i < 4; i++) {
        int j = i * THREADS + tid;
        int row = j >> 4, q = j & 15;
        cp_async16(x_s + row * DIM + ((q ^ (row & 3)) << 2),
                   x + (size_t)(row0 + row) * DIM + q * 4);
    }
#pragma unroll
    for (int i = 0; i < 8; i++) {
        int j = i * THREADS + tid;
        int code = j >> 4, q = j & 15;
        cp_async16(cb_s0 + code * DIM + ((q ^ (code & 15)) << 2),
                   cb + (size_t)code * DIM + q * 4);
    }
    cp_commit();
#pragma unroll
    for (int i = 0; i < 8; i++) {
        int j = i * THREADS + tid;
        int code = j >> 4, q = j & 15;
        cp_async16(cb_s1 + code * DIM + ((q ^ (code & 15)) << 2),
                   cb + (size_t)(BK + code) * DIM + q * 4);
    }
    cp_commit();

    float bestd[4];
    int   besti[4];
#pragma unroll
    for (int r = 0; r < 4; r++) { bestd[r] = __int_as_float(0x7f800000); besti[r] = 0; }

    const float* xp = x_s + (rowbase + rl) * DIM;   // row = rowbase + rl + 4*rr

    for (int t = 0; t < NCHUNK; t++) {
        asm volatile("cp.async.wait_group 1;");
        __syncthreads();
        const float* cbuf = (t & 1) ? cb_s1 : cb_s0;
        const float* cp   = cbuf + (wg_c * 64 + cl) * DIM;   // code = wg_c*64 + cl + 8*cc

        unsigned long long acc[4][8];
#pragma unroll
        for (int r = 0; r < 4; r++)
#pragma unroll
            for (int c = 0; c < 8; c++) acc[r][c] = 0ull;

#pragma unroll
        for (int u = 0; u < 16; u++) {           // 16B unit along D
            const int sux = (u ^ rl) << 2;       // float offset of swizzled unit
            ulonglong2 xv[4];
#pragma unroll
            for (int rr = 0; rr < 4; rr++)
                xv[rr] = *reinterpret_cast<const ulonglong2*>(xp + rr * 4 * DIM + sux);
            const int su0 = (u ^ cl) << 2;
            ulonglong2 cv[8];
#pragma unroll
            for (int cc = 0; cc < 8; cc++) {
                int su = (cc & 1) ? (su0 ^ 32) : su0;   // code bit3 flips swizzle bit
                cv[cc] = *reinterpret_cast<const ulonglong2*>(cp + cc * 8 * DIM + su);
            }
#pragma unroll
            for (int rr = 0; rr < 4; rr++)
#pragma unroll
                for (int cc = 0; cc < 8; cc++) {
                    acc[rr][cc] = ffma2(xv[rr].x, cv[cc].x, acc[rr][cc]);
                    acc[rr][cc] = ffma2(xv[rr].y, cv[cc].y, acc[rr][cc]);
                }
        }

        __syncthreads();   // everyone done reading this buffer
        if (t + 2 < NCHUNK) {
            float* dst = (t & 1) ? cb_s1 : cb_s0;
#pragma unroll
            for (int i = 0; i < 8; i++) {
                int j = i * THREADS + tid;
                int code = j >> 4, q = j & 15;
                cp_async16(dst + code * DIM + ((q ^ (code & 15)) << 2),
                           cb + (size_t)((t + 2) * BK + code) * DIM + q * 4);
            }
        }
        cp_commit();  // empty group legal on last two iterations

        // finalize this chunk's codes (ascending in cc -> strict < keeps lowest idx)
        const int cbase = t * BK + wg_c * 64;
#pragma unroll
        for (int cc = 0; cc < 8; cc++) {
            int code = cbase + cl + 8 * cc;
            float e2v = __ldg(g_e2 + code);
#pragma unroll
            for (int rr = 0; rr < 4; rr++) {
                float dot  = f2lo(acc[rr][cc]) + f2hi(acc[rr][cc]);
                float dist = fmaf(-2.f, dot, e2v);
                if (dist < bestd[rr]) { bestd[rr] = dist; besti[rr] = code; }
            }
        }
    }

    // ---- argmin reduce across the 8 code-lanes (lane bits 2..4) ----
#pragma unroll
    for (int m = 16; m >= 4; m >>= 1) {
#pragma unroll
        for (int rr = 0; rr < 4; rr++) {
            float od = __shfl_xor_sync(0xffffffffu, bestd[rr], m);
            int   oi = __shfl_xor_sync(0xffffffffu, besti[rr], m);
            if (od < bestd[rr] || (od == bestd[rr] && oi < besti[rr])) {
                bestd[rr] = od; besti[rr] = oi;
            }
        }
    }
    // lanes 0..3 (cl==0) hold rows rowbase + lane + 4*rr for this warp's codes
    if (wg_c == 0 && lane < 4) {
#pragma unroll
        for (int rr = 0; rr < 4; rr++) {
            int r = rowbase + lane + 4 * rr;
            s_d[r] = bestd[rr]; s_i[r] = besti[rr];
        }
    }
    __syncthreads();
    if (wg_c == 1 && lane < 4) {
#pragma unroll
        for (int rr = 0; rr < 4; rr++) {
            int r = rowbase + lane + 4 * rr;
            if (bestd[rr] < s_d[r] || (bestd[rr] == s_d[r] && besti[rr] < s_i[r])) {
                s_d[r] = bestd[rr]; s_i[r] = besti[rr];
            }
        }
    }
    __syncthreads();

    if (write_idx && tid < BM) out_idx[row0 + tid] = (float)s_i[tid];

    // cooperative coalesced gather of codebook rows -> x_q
#pragma unroll
    for (int i = 0; i < 4; i++) {
        int j = i * THREADS + tid;
        int row = j >> 4, q = j & 15;
        float4 v = __ldg(reinterpret_cast<const float4*>(cb + (size_t)s_i[row] * DIM) + q);
        reinterpret_cast<float4*>(out_q + (size_t)(row0 + row) * DIM)[q] = v;
    }
}

extern "C" void kernel_launch(void* const* d_in, const int* in_sizes, int n_in,
                              void* d_out, int out_size) {
    const float* x  = (const float*)d_in[0];
    const float* cb = (const float*)d_in[1];
    if (n_in >= 2 && in_sizes[0] == KC * DIM && in_sizes[1] == NROWS * DIM) {
        const float* tmp = x; x = cb; cb = tmp;
    }
    float* out = (float*)d_out;
    int write_idx = (out_size >= NROWS * DIM + NROWS) ? 1 : 0;

    cudaFuncSetAttribute(vq_kernel, cudaFuncAttributeMaxDynamicSharedMemorySize, SMEM_BYTES);

    e2_kernel<<<KC / 256, 256>>>(cb);
    vq_kernel<<<NROWS / BM, THREADS, SMEM_BYTES>>>(x, cb, out, out + (size_t)NROWS * DIM, write_idx);
}